// round 1
// baseline (speedup 1.0000x reference)
#include <cuda_runtime.h>
#include <math.h>

#define Bb 8
#define Nn 16384
#define Dd 768
#define Rr 3
#define NE 4
#define Hh 128
#define Ww 128

// ---------------- device scratch (no allocations allowed) ----------------
__device__ float g_feat[Bb * Rr * Nn];      // xr in planar [b][r][h*128+w]
__device__ float g_part[16384 * Rr];        // per-block partial sums (2048 blocks per b)
__device__ float g_G[Bb * NE];              // gate weights
__device__ float g_d1[Bb * Rr * 64 * 64];
__device__ float g_d2[Bb * Rr * 32 * 32];
__device__ float g_d3[Bb * Rr * 16 * 16];
__device__ float g_c0[Bb * Rr * 128 * 128];
__device__ float g_c1[Bb * Rr * 64 * 64];
__device__ float g_c2[Bb * Rr * 32 * 32];
__device__ float g_c3[Bb * Rr * 16 * 16];
__device__ float g_mixed[Bb * Rr * Nn];     // planar

// ---------------- kernel 1: xr = x@Wd + bd (planar) + partial sums ----------------
// 16384 blocks x 256 threads; warp per row, 8 rows per block (rows of one b only:
// 2048 blocks per b exactly).
__global__ void k1_proj_down(const float* __restrict__ x,
                             const float* __restrict__ Wd,
                             const float* __restrict__ bd) {
    __shared__ float swd[Dd * Rr];   // Wd[d*3+r], stride-3 -> conflict-free for d=lane+32k
    __shared__ float wsum[8][4];     // per-warp row sums (3 used, pad to 4)
    int tid = threadIdx.x;
    for (int i = tid; i < Dd * Rr; i += 256) swd[i] = Wd[i];
    __syncthreads();

    int warp = tid >> 5, lane = tid & 31;
    long row = (long)blockIdx.x * 8 + warp;         // 0..131071
    const float* xp = x + row * Dd;

    float s0 = 0.f, s1 = 0.f, s2 = 0.f;
#pragma unroll
    for (int k = 0; k < 24; k++) {
        int d = lane + 32 * k;
        float xv = __ldg(xp + d);
        s0 = fmaf(xv, swd[d * 3 + 0], s0);
        s1 = fmaf(xv, swd[d * 3 + 1], s1);
        s2 = fmaf(xv, swd[d * 3 + 2], s2);
    }
#pragma unroll
    for (int off = 16; off > 0; off >>= 1) {
        s0 += __shfl_xor_sync(0xFFFFFFFFu, s0, off);
        s1 += __shfl_xor_sync(0xFFFFFFFFu, s1, off);
        s2 += __shfl_xor_sync(0xFFFFFFFFu, s2, off);
    }
    if (lane == 0) {
        wsum[warp][0] = s0 + bd[0];
        wsum[warp][1] = s1 + bd[1];
        wsum[warp][2] = s2 + bd[2];
    }
    __syncthreads();

    // write planar feat: 24 threads, 3 groups of 8 consecutive n
    int b = blockIdx.x >> 11;              // 2048 blocks per b
    int nbase = (blockIdx.x & 2047) * 8;
    if (tid < 24) {
        int r = tid >> 3;
        int w = tid & 7;
        g_feat[((b * Rr + r) * Nn) + nbase + w] = wsum[w][r];
    }
    // deterministic per-block partial sums (fixed order)
    if (tid < 3) {
        float acc = 0.f;
#pragma unroll
        for (int w = 0; w < 8; w++) acc += wsum[w][tid];
        g_part[blockIdx.x * Rr + tid] = acc;
    }
}

// ---------------- kernel 2: reduce mean + gating ----------------
// 1 block, 768 threads = 24 warps; warp w handles (b = w/3, r = w%3)
__global__ void k2_gating(const float* __restrict__ noise,
                          const float* __restrict__ Wg,
                          const float* __restrict__ Wn) {
    __shared__ float sxa[24];
    int warp = threadIdx.x >> 5, lane = threadIdx.x & 31;
    int b = warp / 3, r = warp % 3;
    float s = 0.f;
    for (int i = lane; i < 2048; i += 32)
        s += g_part[(b * 2048 + i) * Rr + r];
#pragma unroll
    for (int off = 16; off > 0; off >>= 1)
        s += __shfl_xor_sync(0xFFFFFFFFu, s, off);
    if (lane == 0) sxa[warp] = s * (1.0f / (float)Nn);
    __syncthreads();

    if (threadIdx.x < Bb) {
        int bb = threadIdx.x;
        float xa0 = sxa[bb * 3 + 0], xa1 = sxa[bb * 3 + 1], xa2 = sxa[bb * 3 + 2];
        float Hlog[NE];
#pragma unroll
        for (int e = 0; e < NE; e++) {
            float hg = xa0 * Wg[0 * NE + e] + xa1 * Wg[1 * NE + e] + xa2 * Wg[2 * NE + e];
            float hn = xa0 * Wn[0 * NE + e] + xa1 * Wn[1 * NE + e] + xa2 * Wn[2 * NE + e];
            float sp = fmaxf(hn, 0.f) + log1pf(expf(-fabsf(hn)));  // softplus
            Hlog[e] = hg + noise[bb * NE + e] * sp;
        }
        // top-2 (first occurrence wins ties, matching lax.top_k)
        int i1 = 0;
#pragma unroll
        for (int e = 1; e < NE; e++) if (Hlog[e] > Hlog[i1]) i1 = e;
        int i2 = -1;
#pragma unroll
        for (int e = 0; e < NE; e++) {
            if (e == i1) continue;
            if (i2 < 0 || Hlog[e] > Hlog[i2]) i2 = e;
        }
        float m = Hlog[i1];
        float e2 = expf(Hlog[i2] - m);
        float invZ = 1.0f / (1.0f + e2);   // masked entries underflow to exact 0
#pragma unroll
        for (int e = 0; e < NE; e++)
            g_G[bb * NE + e] = (e == i1) ? invZ : ((e == i2) ? e2 * invZ : 0.0f);
    }
}

// ---------------- kernel 3a: downsamples (exact 2-tap averages) ----------------
// half-pixel bilinear, factors 2/4/8: src frac is always 0.5 ->
// 128->64: avg rows/cols (2o,2o+1); 128->32: (4o+1,4o+2); 128->16: (8o+3,8o+4)
__global__ void k3a_down() {
    int i = blockIdx.x * blockDim.x + threadIdx.x;
    const int n1 = 24 * 64 * 64, n2 = 24 * 32 * 32, n3 = 24 * 16 * 16;
    if (i < n1) {
        int ch = i / 4096, p = i % 4096;
        int oi = p >> 6, oj = p & 63;
        const float* f = g_feat + ch * Nn;
        int y0 = 2 * oi, x0 = 2 * oj;
        g_d1[i] = 0.25f * (f[y0 * 128 + x0] + f[y0 * 128 + x0 + 1] +
                           f[(y0 + 1) * 128 + x0] + f[(y0 + 1) * 128 + x0 + 1]);
    } else if (i < n1 + n2) {
        int j = i - n1;
        int ch = j / 1024, p = j % 1024;
        int oi = p >> 5, oj = p & 31;
        const float* f = g_feat + ch * Nn;
        int y0 = 4 * oi + 1, x0 = 4 * oj + 1;
        g_d2[j] = 0.25f * (f[y0 * 128 + x0] + f[y0 * 128 + x0 + 1] +
                           f[(y0 + 1) * 128 + x0] + f[(y0 + 1) * 128 + x0 + 1]);
    } else if (i < n1 + n2 + n3) {
        int j = i - n1 - n2;
        int ch = j / 256, p = j % 256;
        int oi = p >> 4, oj = p & 15;
        const float* f = g_feat + ch * Nn;
        int y0 = 8 * oi + 3, x0 = 8 * oj + 3;
        g_d3[j] = 0.25f * (f[y0 * 128 + x0] + f[y0 * 128 + x0 + 1] +
                           f[(y0 + 1) * 128 + x0] + f[(y0 + 1) * 128 + x0 + 1]);
    }
}

// ---------------- kernel 3b: 3x3 depthwise conv (zero pad) on all 4 scales ----------------
__device__ __forceinline__ float conv3x3(const float* __restrict__ src, int S,
                                         int oi, int oj,
                                         const float* __restrict__ k9, float bias) {
    float acc = bias;
#pragma unroll
    for (int di = 0; di < 3; di++) {
        int y = oi + di - 1;
        if ((unsigned)y >= (unsigned)S) continue;
#pragma unroll
        for (int dj = 0; dj < 3; dj++) {
            int xx = oj + dj - 1;
            if ((unsigned)xx >= (unsigned)S) continue;
            acc = fmaf(src[y * S + xx], k9[di * 3 + dj], acc);
        }
    }
    return acc;
}

__global__ void k3b_conv(const float* __restrict__ dwk, const float* __restrict__ dwb) {
    int i = blockIdx.x * blockDim.x + threadIdx.x;
    const int n0 = 24 * 128 * 128, n1 = 24 * 64 * 64, n2 = 24 * 32 * 32, n3 = 24 * 16 * 16;
    if (i < n0) {
        int ch = i / 16384, p = i % 16384;
        int r = ch % 3;
        g_c0[i] = conv3x3(g_feat + ch * 16384, 128, p >> 7, p & 127, dwk + r * 9, dwb[r]);
    } else if (i < n0 + n1) {
        int j = i - n0;
        int ch = j / 4096, p = j % 4096;
        int r = ch % 3;
        g_c1[j] = conv3x3(g_d1 + ch * 4096, 64, p >> 6, p & 63, dwk + r * 9, dwb[r]);
    } else if (i < n0 + n1 + n2) {
        int j = i - n0 - n1;
        int ch = j / 1024, p = j % 1024;
        int r = ch % 3;
        g_c2[j] = conv3x3(g_d2 + ch * 1024, 32, p >> 5, p & 31, dwk + r * 9, dwb[r]);
    } else if (i < n0 + n1 + n2 + n3) {
        int j = i - n0 - n1 - n2;
        int ch = j / 256, p = j % 256;
        int r = ch % 3;
        g_c3[j] = conv3x3(g_d3 + ch * 256, 16, p >> 4, p & 15, dwk + r * 9, dwb[r]);
    }
}

// ---------------- kernel 3c: bilinear upsample + gate-weighted mix ----------------
__device__ __forceinline__ float up_sample(const float* __restrict__ src, int S,
                                           int h, int w, float ratio) {
    // half-pixel, index-clamped (equivalent to jax renormalized edge weights)
    float sy = (h + 0.5f) * ratio - 0.5f;
    float sx = (w + 0.5f) * ratio - 0.5f;
    float fy = floorf(sy), fx = floorf(sx);
    float wy = sy - fy, wx = sx - fx;
    int y0 = (int)fy, x0 = (int)fx;
    int ya = max(y0, 0), yb = min(y0 + 1, S - 1);
    int xa = max(x0, 0), xb = min(x0 + 1, S - 1);
    float v00 = src[ya * S + xa], v01 = src[ya * S + xb];
    float v10 = src[yb * S + xa], v11 = src[yb * S + xb];
    float top = v00 + wx * (v01 - v00);
    float bot = v10 + wx * (v11 - v10);
    return top + wy * (bot - top);
}

__global__ void k3c_mix() {
    int i = blockIdx.x * blockDim.x + threadIdx.x;
    if (i >= 24 * Nn) return;
    int ch = i / Nn, p = i % Nn;
    int b = ch / 3;
    int h = p >> 7, w = p & 127;
    float acc = g_G[b * NE + 0] * g_c0[i];
    acc += g_G[b * NE + 1] * up_sample(g_c1 + ch * 4096, 64, h, w, 0.5f);
    acc += g_G[b * NE + 2] * up_sample(g_c2 + ch * 1024, 32, h, w, 0.25f);
    acc += g_G[b * NE + 3] * up_sample(g_c3 + ch * 256, 16, h, w, 0.125f);
    g_mixed[i] = acc;
}

// ---------------- kernel 4: out = x + mixed @ Wu + bu ----------------
// 16384 blocks x 256 threads; warp per row, float4 streaming
__global__ void k4_out(const float* __restrict__ x,
                       const float* __restrict__ Wu,
                       const float* __restrict__ bu,
                       float* __restrict__ out) {
    __shared__ float swu[Rr * Dd];
    __shared__ float sbu[Dd];
    int tid = threadIdx.x;
    for (int i = tid; i < Rr * Dd; i += 256) swu[i] = Wu[i];
    for (int i = tid; i < Dd; i += 256) sbu[i] = bu[i];
    __syncthreads();

    int warp = tid >> 5, lane = tid & 31;
    long row = (long)blockIdx.x * 8 + warp;
    int b = (int)(row >> 14);
    int n = (int)(row & 16383);
    float m0 = g_mixed[(b * 3 + 0) * Nn + n];
    float m1 = g_mixed[(b * 3 + 1) * Nn + n];
    float m2 = g_mixed[(b * 3 + 2) * Nn + n];

    const float4* xp = (const float4*)(x + row * Dd);
    float4* op = (float4*)(out + row * Dd);
#pragma unroll
    for (int c = 0; c < 6; c++) {
        int d4 = c * 32 + lane;           // float4 index within the row
        int d = d4 * 4;
        float4 xv = __ldg(xp + d4);
        float4 w0 = *(const float4*)&swu[0 * Dd + d];
        float4 w1 = *(const float4*)&swu[1 * Dd + d];
        float4 w2 = *(const float4*)&swu[2 * Dd + d];
        float4 bb = *(const float4*)&sbu[d];
        float4 o;
        o.x = xv.x + fmaf(m0, w0.x, fmaf(m1, w1.x, fmaf(m2, w2.x, bb.x)));
        o.y = xv.y + fmaf(m0, w0.y, fmaf(m1, w1.y, fmaf(m2, w2.y, bb.y)));
        o.z = xv.z + fmaf(m0, w0.z, fmaf(m1, w1.z, fmaf(m2, w2.z, bb.z)));
        o.w = xv.w + fmaf(m0, w0.w, fmaf(m1, w1.w, fmaf(m2, w2.w, bb.w)));
        op[d4] = o;
    }
}

// ---------------- launcher ----------------
extern "C" void kernel_launch(void* const* d_in, const int* in_sizes, int n_in,
                              void* d_out, int out_size) {
    const float* x     = (const float*)d_in[0];
    const float* noise = (const float*)d_in[1];
    const float* Wd    = (const float*)d_in[2];
    const float* bd    = (const float*)d_in[3];
    const float* Wu    = (const float*)d_in[4];
    const float* bu    = (const float*)d_in[5];
    const float* Wg    = (const float*)d_in[6];
    const float* Wn    = (const float*)d_in[7];
    const float* dwk   = (const float*)d_in[8];
    const float* dwb   = (const float*)d_in[9];
    float* out = (float*)d_out;

    k1_proj_down<<<16384, 256>>>(x, Wd, bd);
    k2_gating<<<1, 768>>>(noise, Wg, Wn);
    {
        int total = 24 * (64 * 64 + 32 * 32 + 16 * 16);
        k3a_down<<<(total + 255) / 256, 256>>>();
    }
    {
        int total = 24 * (128 * 128 + 64 * 64 + 32 * 32 + 16 * 16);
        k3b_conv<<<(total + 255) / 256, 256>>>(dwk, dwb);
    }
    k3c_mix<<<(24 * Nn + 255) / 256, 256>>>();
    k4_out<<<16384, 256>>>(x, Wu, bu, out);
}

// round 2
// speedup vs baseline: 1.0676x; 1.0676x over previous
#include <cuda_runtime.h>
#include <math.h>

#define Bb 8
#define Nn 16384
#define Dd 768
#define Rr 3
#define NE 4

// ---------------- device scratch (no allocations allowed) ----------------
__device__ float g_feat[Bb * Rr * Nn];      // xr in planar [b][r][h*128+w]
__device__ float g_part[16384 * Rr];        // per-block partial sums (2048 blocks per b)
__device__ float g_mixed[Bb * Rr * Nn];     // planar

// ---------------- kernel 1: xr = x@Wd + bd (planar) + partial sums ----------------
// 16384 blocks x 256 threads; warp per row (float4), 8 rows per block.
__global__ void k1_proj_down(const float* __restrict__ x,
                             const float* __restrict__ Wd,
                             const float* __restrict__ bd) {
    __shared__ float sw0[Dd], sw1[Dd], sw2[Dd];
    __shared__ float wsum[8][4];
    int tid = threadIdx.x;
    for (int i = tid; i < Dd; i += 256) {
        sw0[i] = Wd[i * 3 + 0];
        sw1[i] = Wd[i * 3 + 1];
        sw2[i] = Wd[i * 3 + 2];
    }
    __syncthreads();

    int warp = tid >> 5, lane = tid & 31;
    long row = (long)blockIdx.x * 8 + warp;         // 0..131071
    const float4* xp = (const float4*)(x + row * Dd);

    float s0 = 0.f, s1 = 0.f, s2 = 0.f;
#pragma unroll
    for (int c = 0; c < 6; c++) {
        int d4 = c * 32 + lane;
        float4 xv = __ldg(xp + d4);
        float4 w0 = *(const float4*)(sw0 + d4 * 4);
        float4 w1 = *(const float4*)(sw1 + d4 * 4);
        float4 w2 = *(const float4*)(sw2 + d4 * 4);
        s0 = fmaf(xv.x, w0.x, fmaf(xv.y, w0.y, fmaf(xv.z, w0.z, fmaf(xv.w, w0.w, s0))));
        s1 = fmaf(xv.x, w1.x, fmaf(xv.y, w1.y, fmaf(xv.z, w1.z, fmaf(xv.w, w1.w, s1))));
        s2 = fmaf(xv.x, w2.x, fmaf(xv.y, w2.y, fmaf(xv.z, w2.z, fmaf(xv.w, w2.w, s2))));
    }
#pragma unroll
    for (int off = 16; off > 0; off >>= 1) {
        s0 += __shfl_xor_sync(0xFFFFFFFFu, s0, off);
        s1 += __shfl_xor_sync(0xFFFFFFFFu, s1, off);
        s2 += __shfl_xor_sync(0xFFFFFFFFu, s2, off);
    }
    if (lane == 0) {
        wsum[warp][0] = s0 + bd[0];
        wsum[warp][1] = s1 + bd[1];
        wsum[warp][2] = s2 + bd[2];
    }
    __syncthreads();

    int b = blockIdx.x >> 11;              // 2048 blocks per b
    int nbase = (blockIdx.x & 2047) * 8;
    if (tid < 24) {
        int r = tid >> 3;
        int w = tid & 7;
        g_feat[((b * Rr + r) * Nn) + nbase + w] = wsum[w][r];
    }
    if (tid < 3) {
        float acc = 0.f;
#pragma unroll
        for (int w = 0; w < 8; w++) acc += wsum[w][tid];
        g_part[blockIdx.x * Rr + tid] = acc;
    }
}

// ---------------- fused middle: gating + pyramid + conv + mix ----------------
__device__ __forceinline__ float conv3x3s(const float* src, int S,
                                          int oi, int oj,
                                          const float* k9, float bias) {
    float acc = bias;
#pragma unroll
    for (int di = 0; di < 3; di++) {
        int y = oi + di - 1;
        if ((unsigned)y >= (unsigned)S) continue;
#pragma unroll
        for (int dj = 0; dj < 3; dj++) {
            int xx = oj + dj - 1;
            if ((unsigned)xx >= (unsigned)S) continue;
            acc = fmaf(src[y * S + xx], k9[di * 3 + dj], acc);
        }
    }
    return acc;
}

__device__ __forceinline__ float up_sample_s(const float* src, int S,
                                             int h, int w, float ratio) {
    // half-pixel, index-clamped (equivalent to jax renormalized edge weights)
    float sy = (h + 0.5f) * ratio - 0.5f;
    float sx = (w + 0.5f) * ratio - 0.5f;
    float fy = floorf(sy), fx = floorf(sx);
    float wy = sy - fy, wx = sx - fx;
    int y0 = (int)fy, x0 = (int)fx;
    int ya = max(y0, 0), yb = min(y0 + 1, S - 1);
    int xa = max(x0, 0), xb = min(x0 + 1, S - 1);
    float v00 = src[ya * S + xa], v01 = src[ya * S + xb];
    float v10 = src[yb * S + xa], v11 = src[yb * S + xb];
    float top = v00 + wx * (v01 - v00);
    float bot = v10 + wx * (v11 - v10);
    return top + wy * (bot - top);
}

// 24 blocks (one per (b,r) plane) x 1024 threads; dynamic smem ~106KB.
__global__ void k3_fused(const float* __restrict__ noise,
                         const float* __restrict__ Wg,
                         const float* __restrict__ Wn,
                         const float* __restrict__ dwk,
                         const float* __restrict__ dwb) {
    extern __shared__ float sm[];
    float* sA  = sm;            // 16384  (feat plane 128x128)
    float* sD1 = sA + 16384;    // 4096   (64x64)
    float* sC1 = sD1 + 4096;    // 4096
    float* sD2 = sC1 + 4096;    // 1024   (32x32)
    float* sC2 = sD2 + 1024;    // 1024
    float* sD3 = sC2 + 1024;    // 256    (16x16)
    float* sC3 = sD3 + 256;     // 256
    __shared__ float sxa[3];
    __shared__ float sG[NE];

    int ch = blockIdx.x;
    int b = ch / 3, r = ch % 3;
    int t = threadIdx.x;

    // load plane (float4)
    {
        const float4* src = (const float4*)(g_feat + ch * Nn);
        float4* dst = (float4*)sA;
        for (int i = t; i < 4096; i += 1024) dst[i] = src[i];
    }

    // gating reduction: warps 0..2, one per rank component (fixed order)
    if (t < 96) {
        int warp = t >> 5, lane = t & 31;
        float s = 0.f;
        for (int i = lane; i < 2048; i += 32)
            s += g_part[(b * 2048 + i) * Rr + warp];
#pragma unroll
        for (int off = 16; off > 0; off >>= 1)
            s += __shfl_xor_sync(0xFFFFFFFFu, s, off);
        if (lane == 0) sxa[warp] = s * (1.0f / (float)Nn);
    }
    __syncthreads();

    if (t == 0) {
        float xa0 = sxa[0], xa1 = sxa[1], xa2 = sxa[2];
        float Hlog[NE];
#pragma unroll
        for (int e = 0; e < NE; e++) {
            float hg = xa0 * Wg[0 * NE + e] + xa1 * Wg[1 * NE + e] + xa2 * Wg[2 * NE + e];
            float hn = xa0 * Wn[0 * NE + e] + xa1 * Wn[1 * NE + e] + xa2 * Wn[2 * NE + e];
            float sp = fmaxf(hn, 0.f) + log1pf(expf(-fabsf(hn)));
            Hlog[e] = hg + noise[b * NE + e] * sp;
        }
        int i1 = 0;
#pragma unroll
        for (int e = 1; e < NE; e++) if (Hlog[e] > Hlog[i1]) i1 = e;
        int i2 = -1;
#pragma unroll
        for (int e = 0; e < NE; e++) {
            if (e == i1) continue;
            if (i2 < 0 || Hlog[e] > Hlog[i2]) i2 = e;
        }
        float e2 = expf(Hlog[i2] - Hlog[i1]);
        float invZ = 1.0f / (1.0f + e2);
#pragma unroll
        for (int e = 0; e < NE; e++)
            sG[e] = (e == i1) ? invZ : ((e == i2) ? e2 * invZ : 0.0f);
    }

    // conv weights in regs (broadcast)
    float k9[9];
#pragma unroll
    for (int j = 0; j < 9; j++) k9[j] = __ldg(dwk + r * 9 + j);
    float bias = __ldg(dwb + r);

    __syncthreads();  // sA fully loaded

    // downsamples from ORIGINAL plane (2-tap avgs; half-pixel frac is exactly 0.5)
    for (int i = t; i < 4096; i += 1024) {
        int oi = i >> 6, oj = i & 63;
        int y0 = 2 * oi, x0 = 2 * oj;
        sD1[i] = 0.25f * (sA[y0 * 128 + x0] + sA[y0 * 128 + x0 + 1] +
                          sA[(y0 + 1) * 128 + x0] + sA[(y0 + 1) * 128 + x0 + 1]);
    }
    {
        int oi = t >> 5, oj = t & 31;   // t < 1024 always
        int y0 = 4 * oi + 1, x0 = 4 * oj + 1;
        sD2[t] = 0.25f * (sA[y0 * 128 + x0] + sA[y0 * 128 + x0 + 1] +
                          sA[(y0 + 1) * 128 + x0] + sA[(y0 + 1) * 128 + x0 + 1]);
    }
    if (t < 256) {
        int oi = t >> 4, oj = t & 15;
        int y0 = 8 * oi + 3, x0 = 8 * oj + 3;
        sD3[t] = 0.25f * (sA[y0 * 128 + x0] + sA[y0 * 128 + x0 + 1] +
                          sA[(y0 + 1) * 128 + x0] + sA[(y0 + 1) * 128 + x0 + 1]);
    }

    // conv on full plane -> registers (no barrier needed: reads only sA)
    float c0r[16];
#pragma unroll
    for (int k = 0; k < 16; k++) {
        int p = k * 1024 + t;
        c0r[k] = conv3x3s(sA, 128, p >> 7, p & 127, k9, bias);
    }

    __syncthreads();  // sD* complete

    for (int i = t; i < 4096; i += 1024)
        sC1[i] = conv3x3s(sD1, 64, i >> 6, i & 63, k9, bias);
    sC2[t] = conv3x3s(sD2, 32, t >> 5, t & 31, k9, bias);
    if (t < 256)
        sC3[t] = conv3x3s(sD3, 16, t >> 4, t & 15, k9, bias);

    __syncthreads();  // sC* + sG complete

    float G0 = sG[0], G1 = sG[1], G2 = sG[2], G3 = sG[3];
#pragma unroll
    for (int k = 0; k < 16; k++) {
        int p = k * 1024 + t;
        int h = p >> 7, w = p & 127;
        float acc = G0 * c0r[k];
        acc += G1 * up_sample_s(sC1, 64, h, w, 0.5f);
        acc += G2 * up_sample_s(sC2, 32, h, w, 0.25f);
        acc += G3 * up_sample_s(sC3, 16, h, w, 0.125f);
        g_mixed[ch * Nn + p] = acc;
    }
}

// ---------------- kernel 4: out = x + mixed @ Wu + bu ----------------
__global__ void k4_out(const float* __restrict__ x,
                       const float* __restrict__ Wu,
                       const float* __restrict__ bu,
                       float* __restrict__ out) {
    __shared__ float swu[Rr * Dd];
    __shared__ float sbu[Dd];
    int tid = threadIdx.x;
    for (int i = tid; i < Rr * Dd; i += 256) swu[i] = Wu[i];
    for (int i = tid; i < Dd; i += 256) sbu[i] = bu[i];
    __syncthreads();

    int warp = tid >> 5, lane = tid & 31;
    long row = (long)blockIdx.x * 8 + warp;
    int b = (int)(row >> 14);
    int n = (int)(row & 16383);
    float m0 = g_mixed[(b * 3 + 0) * Nn + n];
    float m1 = g_mixed[(b * 3 + 1) * Nn + n];
    float m2 = g_mixed[(b * 3 + 2) * Nn + n];

    const float4* xp = (const float4*)(x + row * Dd);
    float4* op = (float4*)(out + row * Dd);
#pragma unroll
    for (int c = 0; c < 6; c++) {
        int d4 = c * 32 + lane;
        int d = d4 * 4;
        float4 xv = __ldg(xp + d4);
        float4 w0 = *(const float4*)&swu[0 * Dd + d];
        float4 w1 = *(const float4*)&swu[1 * Dd + d];
        float4 w2 = *(const float4*)&swu[2 * Dd + d];
        float4 bb = *(const float4*)&sbu[d];
        float4 o;
        o.x = xv.x + fmaf(m0, w0.x, fmaf(m1, w1.x, fmaf(m2, w2.x, bb.x)));
        o.y = xv.y + fmaf(m0, w0.y, fmaf(m1, w1.y, fmaf(m2, w2.y, bb.y)));
        o.z = xv.z + fmaf(m0, w0.z, fmaf(m1, w1.z, fmaf(m2, w2.z, bb.z)));
        o.w = xv.w + fmaf(m0, w0.w, fmaf(m1, w1.w, fmaf(m2, w2.w, bb.w)));
        op[d4] = o;
    }
}

// ---------------- launcher ----------------
extern "C" void kernel_launch(void* const* d_in, const int* in_sizes, int n_in,
                              void* d_out, int out_size) {
    const float* x     = (const float*)d_in[0];
    const float* noise = (const float*)d_in[1];
    const float* Wd    = (const float*)d_in[2];
    const float* bd    = (const float*)d_in[3];
    const float* Wu    = (const float*)d_in[4];
    const float* bu    = (const float*)d_in[5];
    const float* Wg    = (const float*)d_in[6];
    const float* Wn    = (const float*)d_in[7];
    const float* dwk   = (const float*)d_in[8];
    const float* dwb   = (const float*)d_in[9];
    float* out = (float*)d_out;

    const int SMEM3 = (16384 + 4096 * 2 + 1024 * 2 + 256 * 2) * 4;  // 108256 B
    cudaFuncSetAttribute(k3_fused, cudaFuncAttributeMaxDynamicSharedMemorySize, SMEM3);

    k1_proj_down<<<16384, 256>>>(x, Wd, bd);
    k3_fused<<<24, 1024, SMEM3>>>(noise, Wg, Wn, dwk, dwb);
    k4_out<<<16384, 256>>>(x, Wu, bu, out);
}